// round 1
// baseline (speedup 1.0000x reference)
#include <cuda_runtime.h>

// Scratch for column sums: [0..31] = s0 = colsum(U0), [32..63] = s1 = colsum(U1)
__device__ float g_scale[64];

// ---------------------------------------------------------------------------
// Kernel 1: column sums of U0 [N0,32] and U1 [N1,32].
// One block, 256 threads: col = tid%32, part = tid/32 (8 partial sums/col).
// ---------------------------------------------------------------------------
__global__ void colsum_kernel(const float* __restrict__ U0, int n0,
                              const float* __restrict__ U1, int n1) {
    __shared__ float red[256];
    int tid = threadIdx.x;
    int col = tid & 31;
    int part = tid >> 5;

    // --- U0 -> g_scale[0..31] ---
    float acc = 0.0f;
    for (int r = part; r < n0; r += 8) acc += U0[r * 32 + col];
    red[tid] = acc;
    __syncthreads();
    if (part == 0) {
        float s = 0.0f;
#pragma unroll
        for (int p = 0; p < 8; p++) s += red[p * 32 + col];
        g_scale[col] = s;
    }
    __syncthreads();

    // --- U1 -> g_scale[32..63] ---
    acc = 0.0f;
    for (int r = part; r < n1; r += 8) acc += U1[r * 32 + col];
    red[tid] = acc;
    __syncthreads();
    if (part == 0) {
        float s = 0.0f;
#pragma unroll
        for (int p = 0; p < 8; p++) s += red[p * 32 + col];
        g_scale[32 + col] = s;
    }
}

// ---------------------------------------------------------------------------
// Kernel 2: C[P,N] = A[P,32] @ (B[N,32] * s)^T   (s scales K-columns of B,
// equivalent to scaling rows of A). BM=BN=128, 256 threads, 8x8 per thread.
// K=32 lives entirely in SMEM, loaded once per CTA (no global k-loop).
// SMEM is K-major so compute-phase float4 reads are bank-conflict-free.
// ---------------------------------------------------------------------------
__global__ __launch_bounds__(256) void gemm128_kernel(
    const float* __restrict__ A, const float* __restrict__ B, int s_off,
    float* __restrict__ C, int P, int N) {
    __shared__ float As[32][128];
    __shared__ float Bs[32][128];

    const int tid = threadIdx.x;
    const int n0 = blockIdx.x * 128;
    const int p0 = blockIdx.y * 128;
    const float* s = g_scale + s_off;

    // Load A tile [128 rows x 32 k] transposed into As[k][row].
#pragma unroll
    for (int t = 0; t < 4; t++) {
        int idx = tid + 256 * t;          // 0..1023 float4 slots
        int row = idx >> 3;               // 8 float4 per row of 32 floats
        int kq = idx & 7;
        float4 v = make_float4(0.f, 0.f, 0.f, 0.f);
        if (p0 + row < P)
            v = *reinterpret_cast<const float4*>(A + (size_t)(p0 + row) * 32 + kq * 4);
        As[kq * 4 + 0][row] = v.x;
        As[kq * 4 + 1][row] = v.y;
        As[kq * 4 + 2][row] = v.z;
        As[kq * 4 + 3][row] = v.w;
    }
    // Load B tile, scaled by s[k], transposed into Bs[k][row].
#pragma unroll
    for (int t = 0; t < 4; t++) {
        int idx = tid + 256 * t;
        int row = idx >> 3;
        int kq = idx & 7;
        float4 v = make_float4(0.f, 0.f, 0.f, 0.f);
        if (n0 + row < N)
            v = *reinterpret_cast<const float4*>(B + (size_t)(n0 + row) * 32 + kq * 4);
        float4 sv = *reinterpret_cast<const float4*>(s + kq * 4);
        Bs[kq * 4 + 0][row] = v.x * sv.x;
        Bs[kq * 4 + 1][row] = v.y * sv.y;
        Bs[kq * 4 + 2][row] = v.z * sv.z;
        Bs[kq * 4 + 3][row] = v.w * sv.w;
    }
    __syncthreads();

    const int tx = tid & 15;   // 16 thread columns
    const int ty = tid >> 4;   // 16 thread rows

    float acc[8][8];
#pragma unroll
    for (int i = 0; i < 8; i++)
#pragma unroll
        for (int j = 0; j < 8; j++) acc[i][j] = 0.0f;

#pragma unroll
    for (int k = 0; k < 32; k++) {
        float a[8], b[8];
        *reinterpret_cast<float4*>(&a[0]) = *reinterpret_cast<const float4*>(&As[k][ty * 4]);
        *reinterpret_cast<float4*>(&a[4]) = *reinterpret_cast<const float4*>(&As[k][ty * 4 + 64]);
        *reinterpret_cast<float4*>(&b[0]) = *reinterpret_cast<const float4*>(&Bs[k][tx * 4]);
        *reinterpret_cast<float4*>(&b[4]) = *reinterpret_cast<const float4*>(&Bs[k][tx * 4 + 64]);
#pragma unroll
        for (int i = 0; i < 8; i++)
#pragma unroll
            for (int j = 0; j < 8; j++) acc[i][j] = fmaf(a[i], b[j], acc[i][j]);
    }

    // Store: rows = p0 + ty*4 + {0..3, 64..67}; cols = n0 + tx*4 + {0..3, 64..67}.
    // N0=2000, N1=1000 are both divisible by 4 -> float4 col guard is exact.
#pragma unroll
    for (int i = 0; i < 8; i++) {
        int row = p0 + ty * 4 + (i & 3) + (i >> 2) * 64;
        if (row < P) {
            float* crow = C + (size_t)row * N;
            int c0 = n0 + tx * 4;
            if (c0 < N)
                *reinterpret_cast<float4*>(crow + c0) =
                    make_float4(acc[i][0], acc[i][1], acc[i][2], acc[i][3]);
            int c1 = c0 + 64;
            if (c1 < N)
                *reinterpret_cast<float4*>(crow + c1) =
                    make_float4(acc[i][4], acc[i][5], acc[i][6], acc[i][7]);
        }
    }
}

extern "C" void kernel_launch(void* const* d_in, const int* in_sizes, int n_in,
                              void* d_out, int out_size) {
    const float* pt = (const float*)d_in[0];  // [P, 32]
    const float* U0 = (const float*)d_in[1];  // [N0, 32]
    const float* U1 = (const float*)d_in[2];  // [N1, 32]
    const int P  = in_sizes[0] / 32;
    const int N0 = in_sizes[1] / 32;
    const int N1 = in_sizes[2] / 32;

    float* V0 = (float*)d_out;
    float* V1 = V0 + (size_t)P * N0;

    colsum_kernel<<<1, 256>>>(U0, N0, U1, N1);

    dim3 blk(256);
    dim3 g0((N0 + 127) / 128, (P + 127) / 128);
    dim3 g1((N1 + 127) / 128, (P + 127) / 128);
    // V0 = pt @ diag(s1) @ U0^T  -> scale offset 32 (s1)
    gemm128_kernel<<<g0, blk>>>(pt, U0, 32, V0, P, N0);
    // V1 = pt @ diag(s0) @ U1^T  -> scale offset 0 (s0)
    gemm128_kernel<<<g1, blk>>>(pt, U1, 0, V1, P, N1);
}

// round 2
// speedup vs baseline: 1.1728x; 1.1728x over previous
#include <cuda_runtime.h>

// Scratch: g_scale[0..31] = s0 = colsum(U0), [32..63] = s1 = colsum(U1)
__device__ float g_scale[64];
__device__ float g_partial[32][64];   // [block][col-slot]

// ---------------------------------------------------------------------------
// f32x2 packed helpers (Blackwell FFMA2 path — ptxas never auto-fuses)
// ---------------------------------------------------------------------------
__device__ __forceinline__ unsigned long long pack2(float lo, float hi) {
    unsigned long long r;
    asm("mov.b64 %0, {%1, %2};" : "=l"(r) : "f"(lo), "f"(hi));
    return r;
}
__device__ __forceinline__ void unpack2(unsigned long long v, float& lo, float& hi) {
    asm("mov.b64 {%0, %1}, %2;" : "=f"(lo), "=f"(hi) : "l"(v));
}
__device__ __forceinline__ void fma2(unsigned long long& d,
                                     unsigned long long a, unsigned long long b) {
    asm("fma.rn.f32x2 %0, %1, %2, %3;" : "=l"(d) : "l"(a), "l"(b), "l"(d));
}

// ---------------------------------------------------------------------------
// Colsum stage 1: 32 blocks, coalesced grid-stride; per-block partials.
// Element i of U has col = i & 31; stride 8192 is a multiple of 32, so each
// thread's column is fixed -> simple local accumulation, deterministic.
// ---------------------------------------------------------------------------
__global__ void colsum_stage1(const float* __restrict__ U0, int e0,
                              const float* __restrict__ U1, int e1) {
    __shared__ float red[256];
    const int tid = threadIdx.x;
    const int col = tid & 31;
    const int part = tid >> 5;
    const int start = blockIdx.x * 256 + tid;
    const int stride = 32 * 256;

    float acc = 0.0f;
    for (int i = start; i < e0; i += stride) acc += U0[i];
    red[tid] = acc;
    __syncthreads();
    if (part == 0) {
        float s = 0.0f;
#pragma unroll
        for (int p = 0; p < 8; p++) s += red[p * 32 + col];
        g_partial[blockIdx.x][col] = s;
    }
    __syncthreads();

    acc = 0.0f;
    for (int i = start; i < e1; i += stride) acc += U1[i];
    red[tid] = acc;
    __syncthreads();
    if (part == 0) {
        float s = 0.0f;
#pragma unroll
        for (int p = 0; p < 8; p++) s += red[p * 32 + col];
        g_partial[blockIdx.x][32 + col] = s;
    }
}

// Colsum stage 2: fixed-order combine (deterministic).
__global__ void colsum_stage2() {
    int c = threadIdx.x;   // 0..63
    float s = 0.0f;
#pragma unroll
    for (int b = 0; b < 32; b++) s += g_partial[b][c];
    g_scale[c] = s;
}

// ---------------------------------------------------------------------------
// GEMM: C[P,N] = A[P,32] @ (B[N,32] * s)^T.  BM=BN=128, 256 threads,
// 8x8 outputs/thread accumulated as 8x4 f32x2 pairs (FFMA2).
// K=32 fully resident in SMEM, loaded once per CTA. SMEM K-major.
// ---------------------------------------------------------------------------
__global__ __launch_bounds__(256) void gemm128_kernel(
    const float* __restrict__ A, const float* __restrict__ B, int s_off,
    float* __restrict__ C, int P, int N) {
    __shared__ float As[32][128];
    __shared__ float Bs[32][128];

    const int tid = threadIdx.x;
    const int n0 = blockIdx.x * 128;
    const int p0 = blockIdx.y * 128;
    const float* s = g_scale + s_off;

    // Load A tile [128 x 32] transposed into As[k][row].
#pragma unroll
    for (int t = 0; t < 4; t++) {
        int idx = tid + 256 * t;
        int row = idx >> 3;
        int kq = idx & 7;
        float4 v = make_float4(0.f, 0.f, 0.f, 0.f);
        if (p0 + row < P)
            v = *reinterpret_cast<const float4*>(A + (size_t)(p0 + row) * 32 + kq * 4);
        As[kq * 4 + 0][row] = v.x;
        As[kq * 4 + 1][row] = v.y;
        As[kq * 4 + 2][row] = v.z;
        As[kq * 4 + 3][row] = v.w;
    }
    // Load B tile scaled by s[k], transposed into Bs[k][row].
#pragma unroll
    for (int t = 0; t < 4; t++) {
        int idx = tid + 256 * t;
        int row = idx >> 3;
        int kq = idx & 7;
        float4 v = make_float4(0.f, 0.f, 0.f, 0.f);
        if (n0 + row < N)
            v = *reinterpret_cast<const float4*>(B + (size_t)(n0 + row) * 32 + kq * 4);
        float4 sv = *reinterpret_cast<const float4*>(s + kq * 4);
        Bs[kq * 4 + 0][row] = v.x * sv.x;
        Bs[kq * 4 + 1][row] = v.y * sv.y;
        Bs[kq * 4 + 2][row] = v.z * sv.z;
        Bs[kq * 4 + 3][row] = v.w * sv.w;
    }
    __syncthreads();

    const int tx = tid & 15;   // 16 thread columns
    const int ty = tid >> 4;   // 16 thread rows

    unsigned long long acc2[8][4];
    const unsigned long long z = pack2(0.0f, 0.0f);
#pragma unroll
    for (int i = 0; i < 8; i++)
#pragma unroll
        for (int j = 0; j < 4; j++) acc2[i][j] = z;

#pragma unroll
    for (int k = 0; k < 32; k++) {
        float a[8], b[8];
        *reinterpret_cast<float4*>(&a[0]) = *reinterpret_cast<const float4*>(&As[k][ty * 4]);
        *reinterpret_cast<float4*>(&a[4]) = *reinterpret_cast<const float4*>(&As[k][ty * 4 + 64]);
        *reinterpret_cast<float4*>(&b[0]) = *reinterpret_cast<const float4*>(&Bs[k][tx * 4]);
        *reinterpret_cast<float4*>(&b[4]) = *reinterpret_cast<const float4*>(&Bs[k][tx * 4 + 64]);

        unsigned long long bp[4];
        bp[0] = pack2(b[0], b[1]);
        bp[1] = pack2(b[2], b[3]);
        bp[2] = pack2(b[4], b[5]);
        bp[3] = pack2(b[6], b[7]);
#pragma unroll
        for (int i = 0; i < 8; i++) {
            unsigned long long ap = pack2(a[i], a[i]);
#pragma unroll
            for (int j = 0; j < 4; j++) fma2(acc2[i][j], ap, bp[j]);
        }
    }

    // Store (cols divisible by 4 for N0=2000 / N1=1000 -> float4 guard exact).
#pragma unroll
    for (int i = 0; i < 8; i++) {
        int row = p0 + ty * 4 + (i & 3) + (i >> 2) * 64;
        if (row < P) {
            float* crow = C + (size_t)row * N;
            float4 lo, hi;
            unpack2(acc2[i][0], lo.x, lo.y);
            unpack2(acc2[i][1], lo.z, lo.w);
            unpack2(acc2[i][2], hi.x, hi.y);
            unpack2(acc2[i][3], hi.z, hi.w);
            int c0 = n0 + tx * 4;
            if (c0 < N) *reinterpret_cast<float4*>(crow + c0) = lo;
            int c1 = c0 + 64;
            if (c1 < N) *reinterpret_cast<float4*>(crow + c1) = hi;
        }
    }
}

extern "C" void kernel_launch(void* const* d_in, const int* in_sizes, int n_in,
                              void* d_out, int out_size) {
    const float* pt = (const float*)d_in[0];  // [P, 32]
    const float* U0 = (const float*)d_in[1];  // [N0, 32]
    const float* U1 = (const float*)d_in[2];  // [N1, 32]
    const int P  = in_sizes[0] / 32;
    const int N0 = in_sizes[1] / 32;
    const int N1 = in_sizes[2] / 32;

    float* V0 = (float*)d_out;
    float* V1 = V0 + (size_t)P * N0;

    colsum_stage1<<<32, 256>>>(U0, in_sizes[1], U1, in_sizes[2]);
    colsum_stage2<<<1, 64>>>();

    dim3 blk(256);
    dim3 g0((N0 + 127) / 128, (P + 127) / 128);
    dim3 g1((N1 + 127) / 128, (P + 127) / 128);
    // V0 = pt @ diag(s1) @ U0^T  -> s1 at offset 32
    gemm128_kernel<<<g0, blk>>>(pt, U0, 32, V0, P, N0);
    // V1 = pt @ diag(s0) @ U1^T  -> s0 at offset 0
    gemm128_kernel<<<g1, blk>>>(pt, U1, 0, V1, P, N1);
}

// round 4
// speedup vs baseline: 1.5963x; 1.3610x over previous
#include <cuda_runtime.h>
#include <cstdint>

__device__ float g_scale[64];        // [0..31]=s0=colsum(U0), [32..63]=s1=colsum(U1)
__device__ float g_partial[32][64];

// ---------------------------------------------------------------------------
// Column sums (2-stage, deterministic)
// ---------------------------------------------------------------------------
__global__ void colsum_stage1(const float* __restrict__ U0, int e0,
                              const float* __restrict__ U1, int e1) {
    __shared__ float red[256];
    const int tid = threadIdx.x;
    const int col = tid & 31;
    const int part = tid >> 5;
    const int start = blockIdx.x * 256 + tid;
    const int stride = 32 * 256;

    float acc = 0.0f;
    for (int i = start; i < e0; i += stride) acc += U0[i];
    red[tid] = acc;
    __syncthreads();
    if (part == 0) {
        float s = 0.0f;
#pragma unroll
        for (int p = 0; p < 8; p++) s += red[p * 32 + col];
        g_partial[blockIdx.x][col] = s;
    }
    __syncthreads();

    acc = 0.0f;
    for (int i = start; i < e1; i += stride) acc += U1[i];
    red[tid] = acc;
    __syncthreads();
    if (part == 0) {
        float s = 0.0f;
#pragma unroll
        for (int p = 0; p < 8; p++) s += red[p * 32 + col];
        g_partial[blockIdx.x][32 + col] = s;
    }
}

__global__ void colsum_stage2() {
    int c = threadIdx.x;   // 0..63
    float s = 0.0f;
#pragma unroll
    for (int b = 0; b < 32; b++) s += g_partial[b][c];
    g_scale[c] = s;
}

// ---------------------------------------------------------------------------
// tf32 helpers
// ---------------------------------------------------------------------------
__device__ __forceinline__ uint32_t f2tf32(float x) {
    uint32_t r;
    asm("cvt.rna.tf32.f32 %0, %1;" : "=r"(r) : "f"(x));
    return r;
}

__device__ __forceinline__ void mma_tf32(
    float& c0, float& c1, float& c2, float& c3,
    uint32_t a0, uint32_t a1, uint32_t a2, uint32_t a3,
    uint32_t b0, uint32_t b1) {
    asm volatile(
        "mma.sync.aligned.m16n8k8.row.col.f32.tf32.tf32.f32 "
        "{%0,%1,%2,%3}, {%4,%5,%6,%7}, {%8,%9}, {%0,%1,%2,%3};"
        : "+f"(c0), "+f"(c1), "+f"(c2), "+f"(c3)
        : "r"(a0), "r"(a1), "r"(a2), "r"(a3), "r"(b0), "r"(b1));
}

// ---------------------------------------------------------------------------
// Tensor-core GEMM: C[P,N] = A[P,32] @ (B[N,32]*s)^T.
// BM=BN=128, 256 threads = 8 warps (2 m x 4 n), each warp 64x32
// via 4x4 grid of m16n8k8 tf32 mma. K=32 -> 4 k-steps. SMEM K-major, pad 132.
// ---------------------------------------------------------------------------
__global__ __launch_bounds__(256) void gemm_mma(
    const float* __restrict__ A, const float* __restrict__ B, int s_off,
    float* __restrict__ C, int P, int N) {
    __shared__ uint32_t As[32][132];   // tf32 bits, [k][row]
    __shared__ uint32_t Bs[32][132];

    const int tid = threadIdx.x;
    const int n0 = blockIdx.x * 128;
    const int p0 = blockIdx.y * 128;

    // ---- Load + convert tiles ----
    const float* s = g_scale + s_off;
#pragma unroll
    for (int it = 0; it < 4; it++) {
        int slot = it * 256 + tid;     // 1024 float4 slots
        int row = slot >> 3;
        int kq = slot & 7;

        float4 va = make_float4(0.f, 0.f, 0.f, 0.f);
        if (p0 + row < P)
            va = *reinterpret_cast<const float4*>(A + (size_t)(p0 + row) * 32 + kq * 4);
        As[kq * 4 + 0][row] = f2tf32(va.x);
        As[kq * 4 + 1][row] = f2tf32(va.y);
        As[kq * 4 + 2][row] = f2tf32(va.z);
        As[kq * 4 + 3][row] = f2tf32(va.w);

        float4 vb = make_float4(0.f, 0.f, 0.f, 0.f);
        if (n0 + row < N)
            vb = *reinterpret_cast<const float4*>(B + (size_t)(n0 + row) * 32 + kq * 4);
        float4 sv = *reinterpret_cast<const float4*>(s + kq * 4);
        Bs[kq * 4 + 0][row] = f2tf32(vb.x * sv.x);
        Bs[kq * 4 + 1][row] = f2tf32(vb.y * sv.y);
        Bs[kq * 4 + 2][row] = f2tf32(vb.z * sv.z);
        Bs[kq * 4 + 3][row] = f2tf32(vb.w * sv.w);
    }
    __syncthreads();

    const int wid = tid >> 5;
    const int lane = tid & 31;
    const int gid = lane >> 2;        // 0..7
    const int tig = lane & 3;         // 0..3
    const int warp_m = wid & 1;       // 0..1 -> 64 rows each
    const int warp_n = wid >> 1;      // 0..3 -> 32 cols each
    const int mb = warp_m * 64;
    const int nb = warp_n * 32;

    float c[4][4][4];                 // [mt][nt][reg]
#pragma unroll
    for (int mt = 0; mt < 4; mt++)
#pragma unroll
        for (int nt = 0; nt < 4; nt++)
#pragma unroll
            for (int r = 0; r < 4; r++) c[mt][nt][r] = 0.0f;

#pragma unroll
    for (int kk = 0; kk < 4; kk++) {
        const int k0 = kk * 8;
        uint32_t a[4][4], b[4][2];
#pragma unroll
        for (int mt = 0; mt < 4; mt++) {
            int m = mb + mt * 16;
            a[mt][0] = As[k0 + tig][m + gid];
            a[mt][1] = As[k0 + tig][m + gid + 8];
            a[mt][2] = As[k0 + tig + 4][m + gid];
            a[mt][3] = As[k0 + tig + 4][m + gid + 8];
        }
#pragma unroll
        for (int nt = 0; nt < 4; nt++) {
            int n = nb + nt * 8;
            b[nt][0] = Bs[k0 + tig][n + gid];
            b[nt][1] = Bs[k0 + tig + 4][n + gid];
        }
#pragma unroll
        for (int mt = 0; mt < 4; mt++)
#pragma unroll
            for (int nt = 0; nt < 4; nt++)
                mma_tf32(c[mt][nt][0], c[mt][nt][1], c[mt][nt][2], c[mt][nt][3],
                         a[mt][0], a[mt][1], a[mt][2], a[mt][3],
                         b[nt][0], b[nt][1]);
    }

    // ---- Store: float2 per fragment row (4 adjacent lanes = 32B sector) ----
#pragma unroll
    for (int mt = 0; mt < 4; mt++) {
        int row0 = p0 + mb + mt * 16 + gid;
        int row1 = row0 + 8;
#pragma unroll
        for (int nt = 0; nt < 4; nt++) {
            int col = n0 + nb + nt * 8 + tig * 2;
            if (col < N) {
                if (row0 < P)
                    *reinterpret_cast<float2*>(C + (size_t)row0 * N + col) =
                        make_float2(c[mt][nt][0], c[mt][nt][1]);
                if (row1 < P)
                    *reinterpret_cast<float2*>(C + (size_t)row1 * N + col) =
                        make_float2(c[mt][nt][2], c[mt][nt][3]);
            }
        }
    }
}

extern "C" void kernel_launch(void* const* d_in, const int* in_sizes, int n_in,
                              void* d_out, int out_size) {
    const float* pt = (const float*)d_in[0];  // [P, 32]
    const float* U0 = (const float*)d_in[1];  // [N0, 32]
    const float* U1 = (const float*)d_in[2];  // [N1, 32]
    const int P  = in_sizes[0] / 32;
    const int N0 = in_sizes[1] / 32;
    const int N1 = in_sizes[2] / 32;

    float* V0 = (float*)d_out;
    float* V1 = V0 + (size_t)P * N0;

    colsum_stage1<<<32, 256>>>(U0, in_sizes[1], U1, in_sizes[2]);
    colsum_stage2<<<1, 64>>>();

    dim3 blk(256);
    dim3 g0((N0 + 127) / 128, (P + 127) / 128);
    dim3 g1((N1 + 127) / 128, (P + 127) / 128);
    // V0 = pt @ diag(s1) @ U0^T  -> s1 at offset 32
    gemm_mma<<<g0, blk>>>(pt, U0, 32, V0, P, N0);
    // V1 = pt @ diag(s0) @ U1^T  -> s0 at offset 0
    gemm_mma<<<g1, blk>>>(pt, U1, 0, V1, P, N1);
}

// round 5
// speedup vs baseline: 1.8571x; 1.1634x over previous
#include <cuda_runtime.h>
#include <cstdint>

__device__ float g_scale[64];        // [0..31]=s0=colsum(U0), [32..63]=s1=colsum(U1)
__device__ float g_partial[32][64];

// ---------------------------------------------------------------------------
// Column sums (2-stage, deterministic)
// ---------------------------------------------------------------------------
__global__ void colsum_stage1(const float* __restrict__ U0, int e0,
                              const float* __restrict__ U1, int e1) {
    __shared__ float red[256];
    const int tid = threadIdx.x;
    const int col = tid & 31;
    const int part = tid >> 5;
    const int start = blockIdx.x * 256 + tid;
    const int stride = 32 * 256;

    float acc = 0.0f;
    for (int i = start; i < e0; i += stride) acc += U0[i];
    red[tid] = acc;
    __syncthreads();
    if (part == 0) {
        float s = 0.0f;
#pragma unroll
        for (int p = 0; p < 8; p++) s += red[p * 32 + col];
        g_partial[blockIdx.x][col] = s;
    }
    __syncthreads();

    acc = 0.0f;
    for (int i = start; i < e1; i += stride) acc += U1[i];
    red[tid] = acc;
    __syncthreads();
    if (part == 0) {
        float s = 0.0f;
#pragma unroll
        for (int p = 0; p < 8; p++) s += red[p * 32 + col];
        g_partial[blockIdx.x][32 + col] = s;
    }
}

__global__ void colsum_stage2() {
    int c = threadIdx.x;   // 0..63
    float s = 0.0f;
#pragma unroll
    for (int b = 0; b < 32; b++) s += g_partial[b][c];
    g_scale[c] = s;
}

// ---------------------------------------------------------------------------
// tf32 helpers
// ---------------------------------------------------------------------------
__device__ __forceinline__ uint32_t f2tf32(float x) {
    uint32_t r;
    asm("cvt.rna.tf32.f32 %0, %1;" : "=r"(r) : "f"(x));
    return r;
}

__device__ __forceinline__ void mma_tf32(
    float& c0, float& c1, float& c2, float& c3,
    uint32_t a0, uint32_t a1, uint32_t a2, uint32_t a3,
    uint32_t b0, uint32_t b1) {
    asm volatile(
        "mma.sync.aligned.m16n8k8.row.col.f32.tf32.tf32.f32 "
        "{%0,%1,%2,%3}, {%4,%5,%6,%7}, {%8,%9}, {%0,%1,%2,%3};"
        : "+f"(c0), "+f"(c1), "+f"(c2), "+f"(c3)
        : "r"(a0), "r"(a1), "r"(a2), "r"(a3), "r"(b0), "r"(b1));
}

// ---------------------------------------------------------------------------
// Fused GEMM. Grid (3, 391). blockIdx.x: 0,1 -> V0 tiles (U0, s1);
// 2 -> V1 tiles (U1, s0). Each CTA: A-stripe resident, 8 column tiles,
// double-buffered B with register prefetch, SMEM-staged coalesced epilogue.
// SMEM tiles: [row][32] tf32, quad-XOR swizzle w=((k>>2)^(row&7))*4+(k&3).
// ---------------------------------------------------------------------------
__global__ __launch_bounds__(256, 2) void gemm_fused(
    const float* __restrict__ A, const float* __restrict__ U0,
    const float* __restrict__ U1, float* __restrict__ V0,
    float* __restrict__ V1, int P) {
    extern __shared__ float smf[];
    uint32_t* As  = reinterpret_cast<uint32_t*>(smf);          // 128*32
    uint32_t* Bs0 = reinterpret_cast<uint32_t*>(smf) + 4096;
    uint32_t* Bs1 = reinterpret_cast<uint32_t*>(smf) + 8192;
    float*    Cs  = smf + 12288;                               // 32*136

    const int tid = threadIdx.x;
    const int x = blockIdx.x;              // 0,1 -> V0 ; 2 -> V1
    const int p0 = blockIdx.y * 128;

    const float* B = (x == 2) ? U1 : U0;
    float* C       = (x == 2) ? V1 : V0;
    const int N    = (x == 2) ? 1000 : 2000;
    const int tc0  = (x == 2) ? 0 : x * 8; // first column tile index
    const float* s = g_scale + ((x == 2) ? 0 : 32);

    // Per-thread constants for tile loads: kq fixed, rows = it*32 + (tid>>3)
    const int kq = tid & 7;
    const int rbase = tid >> 3;
    const float4 sv = *reinterpret_cast<const float4*>(s + kq * 4);

    // ---- Load A stripe once (swizzled STS.128, conflict-free) ----
#pragma unroll
    for (int it = 0; it < 4; it++) {
        int row = it * 32 + rbase;
        float4 v = make_float4(0.f, 0.f, 0.f, 0.f);
        if (p0 + row < P)
            v = *reinterpret_cast<const float4*>(A + (size_t)(p0 + row) * 32 + kq * 4);
        uint4 t = make_uint4(f2tf32(v.x), f2tf32(v.y), f2tf32(v.z), f2tf32(v.w));
        int w = (kq ^ (row & 7)) << 2;
        *reinterpret_cast<uint4*>(As + row * 32 + w) = t;
    }

    // ---- Prefetch tile 0 and stage into Bs0 ----
    float4 pb[4];
#pragma unroll
    for (int it = 0; it < 4; it++) {
        int row = it * 32 + rbase;
        pb[it] = make_float4(0.f, 0.f, 0.f, 0.f);
        int gn = tc0 * 128 + row;
        if (gn < N)
            pb[it] = *reinterpret_cast<const float4*>(B + (size_t)gn * 32 + kq * 4);
    }
#pragma unroll
    for (int it = 0; it < 4; it++) {
        int row = it * 32 + rbase;
        uint4 t = make_uint4(f2tf32(pb[it].x * sv.x), f2tf32(pb[it].y * sv.y),
                             f2tf32(pb[it].z * sv.z), f2tf32(pb[it].w * sv.w));
        int w = (kq ^ (row & 7)) << 2;
        *reinterpret_cast<uint4*>(Bs0 + row * 32 + w) = t;
    }
    __syncthreads();

    const int wid = tid >> 5;
    const int lane = tid & 31;
    const int gid = lane >> 2;
    const int tig = lane & 3;
    const int warp_m = wid & 1;
    const int mb = warp_m * 64;
    const int nb = (wid >> 1) * 32;

    for (int t = 0; t < 8; t++) {
        uint32_t* Bcur = (t & 1) ? Bs1 : Bs0;
        uint32_t* Bnxt = (t & 1) ? Bs0 : Bs1;
        const int n0 = (tc0 + t) * 128;

        // Prefetch next tile (consumed after epilogue)
        if (t < 7) {
#pragma unroll
            for (int it = 0; it < 4; it++) {
                int row = it * 32 + rbase;
                pb[it] = make_float4(0.f, 0.f, 0.f, 0.f);
                int gn = n0 + 128 + row;
                if (gn < N)
                    pb[it] = *reinterpret_cast<const float4*>(B + (size_t)gn * 32 + kq * 4);
            }
        }

        float c[4][4][4];
#pragma unroll
        for (int mt = 0; mt < 4; mt++)
#pragma unroll
            for (int nt = 0; nt < 4; nt++)
#pragma unroll
                for (int r = 0; r < 4; r++) c[mt][nt][r] = 0.0f;

        // ---- K loop: 4 ksteps of m16n8k8 ----
#pragma unroll
        for (int kk = 0; kk < 4; kk++) {
            const int w0 = (((kk * 2) ^ gid) << 2) + tig;
            const int w1 = (((kk * 2 + 1) ^ gid) << 2) + tig;
            uint32_t a[4][4], b[4][2];
#pragma unroll
            for (int mt = 0; mt < 4; mt++) {
                int m = mb + mt * 16;
                a[mt][0] = As[(m + gid) * 32 + w0];
                a[mt][1] = As[(m + gid + 8) * 32 + w0];
                a[mt][2] = As[(m + gid) * 32 + w1];
                a[mt][3] = As[(m + gid + 8) * 32 + w1];
            }
#pragma unroll
            for (int nt = 0; nt < 4; nt++) {
                int n = nb + nt * 8;
                b[nt][0] = Bcur[(n + gid) * 32 + w0];
                b[nt][1] = Bcur[(n + gid) * 32 + w1];
            }
#pragma unroll
            for (int mt = 0; mt < 4; mt++)
#pragma unroll
                for (int nt = 0; nt < 4; nt++)
                    mma_tf32(c[mt][nt][0], c[mt][nt][1], c[mt][nt][2], c[mt][nt][3],
                             a[mt][0], a[mt][1], a[mt][2], a[mt][3],
                             b[nt][0], b[nt][1]);
        }

        // ---- Epilogue: 4 chunks of 32 rows via Cs (coalesced STG.128) ----
#pragma unroll
        for (int ch = 0; ch < 4; ch++) {
            if (warp_m == (ch >> 1)) {
                int mtb = (ch & 1) * 2;
#pragma unroll
                for (int h = 0; h < 2; h++) {
                    int mt = mtb + h;
                    int r = h * 16 + gid;
#pragma unroll
                    for (int nt = 0; nt < 4; nt++) {
                        int cc = nb + nt * 8 + tig * 2;
                        *reinterpret_cast<float2*>(Cs + r * 136 + cc) =
                            make_float2(c[mt][nt][0], c[mt][nt][1]);
                        *reinterpret_cast<float2*>(Cs + (r + 8) * 136 + cc) =
                            make_float2(c[mt][nt][2], c[mt][nt][3]);
                    }
                }
            }
            __syncthreads();
#pragma unroll
            for (int it = 0; it < 4; it++) {
                int row = it * 8 + wid;
                int gr = p0 + ch * 32 + row;
                int gc = n0 + lane * 4;
                if (gr < P && gc < N) {
                    float4 v = *reinterpret_cast<float4*>(Cs + row * 136 + lane * 4);
                    *reinterpret_cast<float4*>(C + (size_t)gr * N + gc) = v;
                }
            }
            __syncthreads();
        }

        // ---- Stage next B into the other buffer ----
        if (t < 7) {
#pragma unroll
            for (int it = 0; it < 4; it++) {
                int row = it * 32 + rbase;
                uint4 tb = make_uint4(f2tf32(pb[it].x * sv.x), f2tf32(pb[it].y * sv.y),
                                      f2tf32(pb[it].z * sv.z), f2tf32(pb[it].w * sv.w));
                int w = (kq ^ (row & 7)) << 2;
                *reinterpret_cast<uint4*>(Bnxt + row * 32 + w) = tb;
            }
        }
        __syncthreads();
    }
}

extern "C" void kernel_launch(void* const* d_in, const int* in_sizes, int n_in,
                              void* d_out, int out_size) {
    const float* pt = (const float*)d_in[0];  // [P, 32]
    const float* U0 = (const float*)d_in[1];  // [N0, 32]
    const float* U1 = (const float*)d_in[2];  // [N1, 32]
    const int P  = in_sizes[0] / 32;
    const int N0 = in_sizes[1] / 32;
    const int N1 = in_sizes[2] / 32;

    float* V0 = (float*)d_out;
    float* V1 = V0 + (size_t)P * N0;

    const int smem_bytes = (4096 * 3) * 4 + 32 * 136 * 4;  // 66560
    cudaFuncSetAttribute(gemm_fused, cudaFuncAttributeMaxDynamicSharedMemorySize,
                         smem_bytes);

    colsum_stage1<<<32, 256>>>(U0, in_sizes[1], U1, in_sizes[2]);
    colsum_stage2<<<1, 64>>>();

    dim3 grid(3, (P + 127) / 128);
    gemm_fused<<<grid, 256, smem_bytes>>>(pt, U0, U1, V0, V1, P);
}